// round 9
// baseline (speedup 1.0000x reference)
#include <cuda_runtime.h>
#include <cuda_bf16.h>
#include <cstdint>

#define NPTS 65536
#define KC   4096
#define DIM  128
#define BN   128          // n rows per CTA
#define BK   128          // centroids per k-tile
#define KHALF 2048        // k range per CTA
#define NT   (KHALF / BK) // 16 tiles

// Device scratch (allocation-free rule)
__device__ __nv_bfloat16 g_a0[NPTS * DIM];
__device__ __nv_bfloat16 g_a1[NPTS * DIM];
__device__ __nv_bfloat16 g_b0[KC * DIM];
__device__ __nv_bfloat16 g_b1[KC * DIM];
__device__ float g_c2[KC];
__device__ float g_na[NPTS], g_na1[NPTS], g_nra2[NPTS];   // row norms (A)
__device__ float g_nb[KC],  g_nb1[KC],  g_nrb2[KC];        // row norms (B)
__device__ float g_bmax[4];                                 // max of b-norms
__device__ float4 g_half[2][NPTS];   // per k-half: {best, second, idx_bits, 0}
__device__ int   g_list[NPTS];
__device__ int   g_count[1];

// ---------------------------------------------------------------------------
__device__ __forceinline__ uint32_t smem_u32(const void* p) {
    uint32_t a;
    asm("{ .reg .u64 t; cvta.to.shared.u64 t, %1; cvt.u32.u64 %0, t; }"
        : "=r"(a) : "l"(p));
    return a;
}
#define LDSM_X4(r0, r1, r2, r3, addr) \
    asm volatile("ldmatrix.sync.aligned.m8n8.x4.shared.b16 {%0,%1,%2,%3}, [%4];" \
                 : "=r"(r0), "=r"(r1), "=r"(r2), "=r"(r3) : "r"(addr))
#define MMA_BF16(c, a, b0v, b1v) \
    asm volatile("mma.sync.aligned.m16n8k16.row.col.f32.bf16.bf16.f32 " \
                 "{%0,%1,%2,%3}, {%4,%5,%6,%7}, {%8,%9}, {%0,%1,%2,%3};" \
                 : "+f"((c)[0]), "+f"((c)[1]), "+f"((c)[2]), "+f"((c)[3]) \
                 : "r"((a)[0]), "r"((a)[1]), "r"((a)[2]), "r"((a)[3]), \
                   "r"(b0v), "r"(b1v))
__device__ __forceinline__ void cp16(uint32_t dst, const void* src) {
    asm volatile("cp.async.cg.shared.global [%0], [%1], 16;"
                 :: "r"(dst), "l"(src));
}
#define CP_COMMIT() asm volatile("cp.async.commit_group;" ::: "memory")
#define CP_WAIT0()  asm volatile("cp.async.wait_group 0;" ::: "memory")

// ---------------------------------------------------------------------------
// Prologue: warp-per-row 2-way bf16 split + exact residual norms.
// ---------------------------------------------------------------------------
__device__ __forceinline__ void split4(const float4 v, __nv_bfloat16* p0,
                                       __nv_bfloat16* p1, float& s_a,
                                       float& s_a1, float& s_r2) {
    float va[4] = {v.x, v.y, v.z, v.w};
    #pragma unroll
    for (int i = 0; i < 4; ++i) {
        float x = va[i];
        __nv_bfloat16 h0 = __float2bfloat16(x);
        float r1 = x - __bfloat162float(h0);
        __nv_bfloat16 h1 = __float2bfloat16(r1);
        float r2 = r1 - __bfloat162float(h1);
        float a1f = __bfloat162float(h1);
        s_a  = fmaf(x, x, s_a);
        s_a1 = fmaf(a1f, a1f, s_a1);
        s_r2 = fmaf(r2, r2, s_r2);
        p0[i] = h0; p1[i] = h1;
    }
}
__device__ __forceinline__ float wsum(float s) {
    #pragma unroll
    for (int o = 16; o; o >>= 1) s += __shfl_xor_sync(0xFFFFFFFFu, s, o);
    return s;
}

__global__ void split_lat_kernel(const float* __restrict__ in) {
    int row  = blockIdx.x * 8 + (threadIdx.x >> 5);
    int lane = threadIdx.x & 31;
    float4 v = ((const float4*)(in + (size_t)row * DIM))[lane];
    __nv_bfloat16 p0[4], p1[4];
    float s_a = 0.f, s_a1 = 0.f, s_r2 = 0.f;
    split4(v, p0, p1, s_a, s_a1, s_r2);
    *(uint2*)(g_a0 + (size_t)row * DIM + lane * 4) = *(const uint2*)p0;
    *(uint2*)(g_a1 + (size_t)row * DIM + lane * 4) = *(const uint2*)p1;
    s_a = wsum(s_a); s_a1 = wsum(s_a1); s_r2 = wsum(s_r2);
    if (lane == 0) {
        g_na[row]   = sqrtf(s_a);
        g_na1[row]  = sqrtf(s_a1);
        g_nra2[row] = sqrtf(s_r2);
    }
}
__global__ void split_coo_kernel(const float* __restrict__ in) {
    int row  = blockIdx.x * 8 + (threadIdx.x >> 5);
    int lane = threadIdx.x & 31;
    float4 v = ((const float4*)(in + (size_t)row * DIM))[lane];
    __nv_bfloat16 p0[4], p1[4];
    float s_b = 0.f, s_b1 = 0.f, s_r2 = 0.f;
    split4(v, p0, p1, s_b, s_b1, s_r2);
    *(uint2*)(g_b0 + (size_t)row * DIM + lane * 4) = *(const uint2*)p0;
    *(uint2*)(g_b1 + (size_t)row * DIM + lane * 4) = *(const uint2*)p1;
    s_b = wsum(s_b); s_b1 = wsum(s_b1); s_r2 = wsum(s_r2);
    if (lane == 0) {
        g_c2[row]   = s_b;            // ||c||^2 (exact fp32)
        g_nb[row]   = sqrtf(s_b);
        g_nb1[row]  = sqrtf(s_b1);
        g_nrb2[row] = sqrtf(s_r2);
    }
}
// max-reduce b-norms + reset list counter
__global__ void reduce_kernel() {
    __shared__ float sm0[512], sm1[512], sm2[512];
    int t = threadIdx.x;
    float m0 = 0.f, m1 = 0.f, m2 = 0.f;
    for (int k = t; k < KC; k += 512) {
        m0 = fmaxf(m0, g_nb[k]);
        m1 = fmaxf(m1, g_nb1[k]);
        m2 = fmaxf(m2, g_nrb2[k]);
    }
    sm0[t] = m0; sm1[t] = m1; sm2[t] = m2;
    __syncthreads();
    for (int o = 256; o; o >>= 1) {
        if (t < o) {
            sm0[t] = fmaxf(sm0[t], sm0[t + o]);
            sm1[t] = fmaxf(sm1[t], sm1[t + o]);
            sm2[t] = fmaxf(sm2[t], sm2[t + o]);
        }
        __syncthreads();
    }
    if (t == 0) {
        g_bmax[0] = sm0[0]; g_bmax[1] = sm1[0]; g_bmax[2] = sm2[0];
        g_count[0] = 0;
    }
}

// ---------------------------------------------------------------------------
// Main: HMMA bf16 3-pass split GEMM + fused top-2 argmin per k-half.
// 256 threads = warp grid 4(M) x 2(N); warp tile 32(M) x 64(N).
// smem: A0 @0, A1 @32K; B[st][pl] @ 64K + st*64K + pl*32K (192 KB).
// ---------------------------------------------------------------------------
__global__ __launch_bounds__(256, 1) void nn_hmma_kernel() {
    extern __shared__ char smem[];
    const uint32_t sbase = smem_u32(smem);

    const int tid = threadIdx.x;
    const int L   = tid & 31;
    const int wid = tid >> 5;
    const int wm  = wid >> 1;
    const int wn  = wid & 1;
    const int n0   = (blockIdx.x >> 1) * BN;
    const int half = blockIdx.x & 1;
    const int kb   = half * KHALF;

    // ---- stage A splits once ----
    {
        const __nv_bfloat16* gA[2] = {g_a0, g_a1};
        #pragma unroll
        for (int s = 0; s < 2; ++s)
            #pragma unroll
            for (int it = 0; it < 8; ++it) {
                int Gi = tid + it * 256;
                int row = Gi >> 4, g = Gi & 15;
                uint4 v = *((const uint4*)(gA[s] + (size_t)(n0 + row) * DIM) + g);
                *(uint4*)(smem + s * 32768 + row * 256 + ((g ^ (row & 7)) << 4)) = v;
            }
    }

    auto stage_b = [&](int st, int k0) {
        #pragma unroll
        for (int s = 0; s < 2; ++s) {
            const __nv_bfloat16* gb = s ? g_b1 : g_b0;
            #pragma unroll
            for (int it = 0; it < 8; ++it) {
                int Gi = tid + it * 256;
                int row = Gi >> 4, g = Gi & 15;
                uint32_t dst = sbase + 65536 + st * 65536 + s * 32768 +
                               row * 256 + ((g ^ (row & 7)) << 4);
                cp16(dst, gb + (size_t)(k0 + row) * DIM + g * 8);
            }
        }
    };
    stage_b(0, kb);
    CP_COMMIT();

    const int aBase = 32 * wm + ((L >> 3) & 1) * 8 + (L & 7);
    const int aG    = (L >> 4);
    const int sxa   = aBase & 7;
    const int bBase = 64 * wn + (L >> 4) * 8 + (L & 7);
    const int bG    = (L >> 3) & 1;
    const int sxb   = bBase & 7;
    const uint32_t aAddr0 = sbase + aBase * 256;

    // top-2 tracking per row-slot
    float v1[4], v2[4];
    int   i1[4];
    #pragma unroll
    for (int i = 0; i < 4; ++i) { v1[i] = 3.0e38f; v2[i] = 3.0e38f; i1[i] = 0; }

    for (int kt = 0; kt < NT; ++kt) {
        const int st = kt & 1;
        const int k0 = kb + kt * BK;

        CP_WAIT0();
        __syncthreads();
        if (kt + 1 < NT) { stage_b(st ^ 1, k0 + BK); CP_COMMIT(); }

        const uint32_t bAddr = sbase + 65536 + st * 65536 + bBase * 256;

        float acc[2][8][4];
        #pragma unroll
        for (int bi = 0; bi < 2; ++bi)
            #pragma unroll
            for (int nb = 0; nb < 8; ++nb)
                #pragma unroll
                for (int c = 0; c < 4; ++c) acc[bi][nb][c] = 0.0f;

        #pragma unroll
        for (int kk = 0; kk < 8; ++kk) {
            uint32_t a[2][2][4];
            #pragma unroll
            for (int pl = 0; pl < 2; ++pl)
                #pragma unroll
                for (int bi = 0; bi < 2; ++bi) {
                    uint32_t ad = aAddr0 + pl * 32768 + bi * 4096 +
                                  (((2 * kk + aG) ^ sxa) << 4);
                    LDSM_X4(a[pl][bi][0], a[pl][bi][1], a[pl][bi][2], a[pl][bi][3], ad);
                }
            uint32_t b[2][4][4];
            #pragma unroll
            for (int pl = 0; pl < 2; ++pl)
                #pragma unroll
                for (int i = 0; i < 4; ++i) {
                    uint32_t bd = bAddr + pl * 32768 + i * 4096 +
                                  (((2 * kk + bG) ^ sxb) << 4);
                    LDSM_X4(b[pl][i][0], b[pl][i][1], b[pl][i][2], b[pl][i][3], bd);
                }
            // 3 split products: A0B0 + A1B0 + A0B1 (A1B1 bounded & fixed up)
            #pragma unroll
            for (int pr = 0; pr < 3; ++pr) {
                const int ap = (pr == 1) ? 1 : 0;
                const int bp = (pr == 2) ? 1 : 0;
                #pragma unroll
                for (int bi = 0; bi < 2; ++bi)
                    #pragma unroll
                    for (int nb = 0; nb < 8; ++nb) {
                        const uint32_t* q = b[bp][nb >> 1];
                        if (nb & 1) MMA_BF16(acc[bi][nb], a[ap][bi], q[2], q[3]);
                        else        MMA_BF16(acc[bi][nb], a[ap][bi], q[0], q[1]);
                    }
            }
        }

        // ---- fused top-2 epilogue (k ascends per slot; strict '<' keeps
        //      first occurrence) ----
        #pragma unroll
        for (int bi = 0; bi < 2; ++bi)
            #pragma unroll
            for (int nb = 0; nb < 8; ++nb) {
                int ncol = 64 * wn + 8 * nb + 2 * (L & 3);
                float2 c2p = __ldg((const float2*)(g_c2 + k0 + ncol));
                int kidx = k0 + ncol;
                #pragma unroll
                for (int h = 0; h < 2; ++h) {
                    int r = bi * 2 + h;
                    float s0 = fmaf(-2.0f, acc[bi][nb][h * 2 + 0], c2p.x);
                    float s1 = fmaf(-2.0f, acc[bi][nb][h * 2 + 1], c2p.y);
                    if (s0 < v1[r]) { v2[r] = v1[r]; v1[r] = s0; i1[r] = kidx; }
                    else if (s0 < v2[r]) v2[r] = s0;
                    if (s1 < v1[r]) { v2[r] = v1[r]; v1[r] = s1; i1[r] = kidx + 1; }
                    else if (s1 < v2[r]) v2[r] = s1;
                }
            }
    }

    // ---- intra-CTA top-2 merge (8 slots per row) ----
    __syncthreads();
    float* rv1 = (float*)smem;                        // [128][8]
    float* rv2 = (float*)(smem + 4096);               // [128][8]
    int*   rid = (int*)(smem + 8192);                 // [128][8]
    #pragma unroll
    for (int bi = 0; bi < 2; ++bi)
        #pragma unroll
        for (int h = 0; h < 2; ++h) {
            int row  = 32 * wm + 16 * bi + 8 * h + (L >> 2);
            int slot = wn * 4 + (L & 3);
            rv1[row * 8 + slot] = v1[bi * 2 + h];
            rv2[row * 8 + slot] = v2[bi * 2 + h];
            rid[row * 8 + slot] = i1[bi * 2 + h];
        }
    __syncthreads();
    if (tid < BN) {
        float b1 = 3.0e38f, b2 = 3.0e38f;
        int   bi = 0x7FFFFFFF;
        #pragma unroll
        for (int c = 0; c < 8; ++c) {
            float v  = rv1[tid * 8 + c];
            int   id = rid[tid * 8 + c];
            if (v < b1) { b2 = b1; b1 = v; bi = id; }
            else { b2 = fminf(b2, v); if (v == b1 && id < bi) bi = id; }
        }
        #pragma unroll
        for (int c = 0; c < 8; ++c) b2 = fminf(b2, rv2[tid * 8 + c]);
        g_half[half][n0 + tid] = make_float4(b1, b2, __int_as_float(bi), 0.f);
    }
}

// ---------------------------------------------------------------------------
// Fixup: merge the two k-halves, certify via the error bound; list the rest.
// ---------------------------------------------------------------------------
__global__ void fixup_kernel(float* __restrict__ out) {
    int i = blockIdx.x * blockDim.x + threadIdx.x;
    if (i >= NPTS) return;
    float4 h0 = g_half[0][i];
    float4 h1 = g_half[1][i];
    float b1 = h0.x, b2 = h0.y;
    int   bi = __float_as_int(h0.z);
    float v  = h1.x;
    if (v < b1) { b2 = fminf(b2, b1); b1 = v; bi = __float_as_int(h1.z); }
    else b2 = fminf(b2, v);           // tie keeps half0 (lower idx)
    b2 = fminf(b2, h1.y);

    // |score err| <= 2*(||a1||*max||b1|| + ||a||*max||rb2|| + max||b||*||ra2||
    //                + ||ra2||*max||rb2|| + acc);  margin covers 2 candidates.
    float na = g_na[i], na1 = g_na1[i], nra2 = g_nra2[i];
    float bm = g_bmax[0], bm1 = g_bmax[1], bm2 = g_bmax[2];
    float err = na1 * bm1 + na * bm2 + bm * nra2 + nra2 * bm2
              + 3.8e-6f * na * bm;    // fp32 accumulation slack (~2^-18)
    float margin = 4.0f * err + 1e-4f;

    if (b2 - b1 > margin) {
        out[i] = (float)bi;
    } else {
        int p = atomicAdd(g_count, 1);
        g_list[p] = i;
    }
}

// ---------------------------------------------------------------------------
// Exact re-solve for undecided rows (fp32, full 4096 scan, first-occurrence).
// ---------------------------------------------------------------------------
__global__ void exact_kernel(const float* __restrict__ latent,
                             const float* __restrict__ coords,
                             float* __restrict__ out) {
    __shared__ float xr[DIM];
    __shared__ float sv[128];
    __shared__ int   si[128];
    const int t = threadIdx.x;
    const int total = g_count[0];

    for (int ci = blockIdx.x; ci < total; ci += gridDim.x) {
        int n = g_list[ci];
        __syncthreads();
        if (t < 32) ((float4*)xr)[t] = ((const float4*)(latent + (size_t)n * DIM))[t];
        __syncthreads();

        float bv = 3.0e38f;
        int   bi = 0;
        for (int k = t; k < KC; k += 128) {
            const float* c = coords + (size_t)k * DIM;
            float dot = 0.f;
            #pragma unroll 8
            for (int d = 0; d < DIM; ++d) dot = fmaf(xr[d], __ldg(c + d), dot);
            float s = fmaf(-2.0f, dot, g_c2[k]);
            if (s < bv) { bv = s; bi = k; }     // k ascends per thread
        }
        sv[t] = bv; si[t] = bi;
        __syncthreads();
        for (int o = 64; o; o >>= 1) {
            if (t < o) {
                float ov = sv[t + o]; int oi = si[t + o];
                if (ov < sv[t] || (ov == sv[t] && oi < si[t])) {
                    sv[t] = ov; si[t] = oi;
                }
            }
            __syncthreads();
        }
        if (t == 0) out[n] = (float)si[0];
    }
}

// ---------------------------------------------------------------------------
extern "C" void kernel_launch(void* const* d_in, const int* in_sizes, int n_in,
                              void* d_out, int out_size) {
    const float* latent;
    const float* coords;
    if (in_sizes[0] == NPTS * DIM) {
        latent = (const float*)d_in[0];
        coords = (const float*)d_in[1];
    } else {
        latent = (const float*)d_in[1];
        coords = (const float*)d_in[0];
    }
    float* out = (float*)d_out;

    const int smem_bytes = 196608;   // A 64K + B 2x64K
    cudaFuncSetAttribute(nn_hmma_kernel,
                         cudaFuncAttributeMaxDynamicSharedMemorySize, smem_bytes);

    split_lat_kernel<<<NPTS / 8, 256>>>(latent);
    split_coo_kernel<<<KC / 8, 256>>>(coords);
    reduce_kernel<<<1, 512>>>();
    nn_hmma_kernel<<<(NPTS / BN) * 2, 256, smem_bytes>>>();
    fixup_kernel<<<NPTS / 256, 256>>>(out);
    exact_kernel<<<256, 128>>>(latent, coords, out);
}

// round 10
// speedup vs baseline: 1.5528x; 1.5528x over previous
#include <cuda_runtime.h>
#include <cuda_bf16.h>
#include <cstdint>

#define NPTS 65536
#define KC   4096
#define DIM  128
#define BN   128          // n rows per CTA
#define BK   128          // centroids per k-tile
#define KHALF 2048        // k range per CTA
#define NT   (KHALF / BK) // 16 tiles
#define NTHREADS 512

// Device scratch (allocation-free rule)
__device__ __nv_bfloat16 g_a0[NPTS * DIM];
__device__ __nv_bfloat16 g_a1[NPTS * DIM];
__device__ __nv_bfloat16 g_b0[KC * DIM];
__device__ __nv_bfloat16 g_b1[KC * DIM];
__device__ float         g_c2[KC];
__device__ unsigned long long g_best[NPTS];   // (fkey(score) << 32) | idx

// ---------------------------------------------------------------------------
__device__ __forceinline__ uint32_t smem_u32(const void* p) {
    uint32_t a;
    asm("{ .reg .u64 t; cvta.to.shared.u64 t, %1; cvt.u32.u64 %0, t; }"
        : "=r"(a) : "l"(p));
    return a;
}
__device__ __forceinline__ uint32_t fkey(float f) {      // order-preserving
    uint32_t u = __float_as_uint(f);
    return (u & 0x80000000u) ? ~u : (u | 0x80000000u);
}
#define LDSM_X4(r0, r1, r2, r3, addr) \
    asm volatile("ldmatrix.sync.aligned.m8n8.x4.shared.b16 {%0,%1,%2,%3}, [%4];" \
                 : "=r"(r0), "=r"(r1), "=r"(r2), "=r"(r3) : "r"(addr))
#define MMA_BF16(c, a, b0v, b1v) \
    asm volatile("mma.sync.aligned.m16n8k16.row.col.f32.bf16.bf16.f32 " \
                 "{%0,%1,%2,%3}, {%4,%5,%6,%7}, {%8,%9}, {%0,%1,%2,%3};" \
                 : "+f"((c)[0]), "+f"((c)[1]), "+f"((c)[2]), "+f"((c)[3]) \
                 : "r"((a)[0]), "r"((a)[1]), "r"((a)[2]), "r"((a)[3]), \
                   "r"(b0v), "r"(b1v))
__device__ __forceinline__ void cp16(uint32_t dst, const void* src) {
    asm volatile("cp.async.cg.shared.global [%0], [%1], 16;"
                 :: "r"(dst), "l"(src));
}
#define CP_COMMIT() asm volatile("cp.async.commit_group;" ::: "memory")
#define CP_WAIT0()  asm volatile("cp.async.wait_group 0;" ::: "memory")

// ---------------------------------------------------------------------------
// Prologues (identical math to R8)
// ---------------------------------------------------------------------------
__global__ void split_lat_kernel(const float* __restrict__ in) {
    int i = blockIdx.x * blockDim.x + threadIdx.x;
    if (i >= NPTS * DIM) return;
    float v = in[i];
    __nv_bfloat16 b0 = __float2bfloat16(v);
    float r1 = v - __bfloat162float(b0);
    g_a0[i] = b0; g_a1[i] = __float2bfloat16(r1);
}
__global__ void split_coo_kernel(const float* __restrict__ in) {
    int i = blockIdx.x * blockDim.x + threadIdx.x;
    if (i >= KC * DIM) return;
    float v = in[i];
    __nv_bfloat16 b0 = __float2bfloat16(v);
    float r1 = v - __bfloat162float(b0);
    g_b0[i] = b0; g_b1[i] = __float2bfloat16(r1);
}
__global__ void c2_kernel(const float* __restrict__ coords) {
    int row  = blockIdx.x * 8 + (threadIdx.x >> 5);
    int lane = threadIdx.x & 31;
    float4 v = ((const float4*)(coords + (size_t)row * DIM))[lane];
    float s = fmaf(v.x, v.x, fmaf(v.y, v.y, fmaf(v.z, v.z, v.w * v.w)));
    #pragma unroll
    for (int o = 16; o; o >>= 1) s += __shfl_xor_sync(0xFFFFFFFFu, s, o);
    if (lane == 0) g_c2[row] = s;
}
__global__ void init_best_kernel() {
    int i = blockIdx.x * blockDim.x + threadIdx.x;
    if (i < NPTS) g_best[i] = 0xFFFFFFFFFFFFFFFFull;
}
__global__ void final_kernel(float* __restrict__ out) {
    int i = blockIdx.x * blockDim.x + threadIdx.x;
    if (i < NPTS) out[i] = (float)(uint32_t)(g_best[i] & 0xFFFFFFFFull);
}

// ---------------------------------------------------------------------------
// Main: HMMA bf16 2x2-split GEMM + fused argmin, cp.async double-buffered B.
// 512 threads = warp grid 4(M) x 4(N); warp tile 32(M) x 32(N).
// smem: A0 @0, A1 @32K; B[st][pl] @ 64K + st*64K + pl*32K (192 KB total).
// Plane layout: 256B rows (128 bf16), 16B granule swizzle g ^= (row & 7).
// ---------------------------------------------------------------------------
__global__ __launch_bounds__(NTHREADS, 1) void nn_hmma_kernel() {
    extern __shared__ char smem[];
    const uint32_t sbase = smem_u32(smem);

    const int tid = threadIdx.x;
    const int L   = tid & 31;
    const int wid = tid >> 5;       // 0..15
    const int wm  = wid & 3;        // 4 M groups (32 rows each)
    const int wn  = wid >> 2;       // 4 N groups (32 cols each)
    const int n0  = (blockIdx.x >> 1) * BN;
    const int kb  = (blockIdx.x & 1) * KHALF;

    // ---- stage A splits once ----
    {
        const __nv_bfloat16* gA[2] = {g_a0, g_a1};
        #pragma unroll
        for (int s = 0; s < 2; ++s)
            #pragma unroll
            for (int it = 0; it < 4; ++it) {
                int Gi = tid + it * NTHREADS;       // 0..2047
                int row = Gi >> 4, g = Gi & 15;
                uint4 v = *((const uint4*)(gA[s] + (size_t)(n0 + row) * DIM) + g);
                *(uint4*)(smem + s * 32768 + row * 256 + ((g ^ (row & 7)) << 4)) = v;
            }
    }

    auto stage_b = [&](int st, int k0) {
        #pragma unroll
        for (int s = 0; s < 2; ++s) {
            const __nv_bfloat16* gb = s ? g_b1 : g_b0;
            #pragma unroll
            for (int it = 0; it < 4; ++it) {
                int Gi = tid + it * NTHREADS;
                int row = Gi >> 4, g = Gi & 15;
                uint32_t dst = sbase + 65536 + st * 65536 + s * 32768 +
                               row * 256 + ((g ^ (row & 7)) << 4);
                cp16(dst, gb + (size_t)(k0 + row) * DIM + g * 8);
            }
        }
    };
    stage_b(0, kb);
    CP_COMMIT();

    // ldmatrix lane-address constants (same per-warp scheme as R7/R8)
    const int aBase = 32 * wm + ((L >> 3) & 1) * 8 + (L & 7);
    const int aG    = (L >> 4);
    const int sxa   = aBase & 7;
    const int bBase = 32 * wn + (L >> 4) * 8 + (L & 7);
    const int bG    = (L >> 3) & 1;
    const int sxb   = bBase & 7;
    const uint32_t aAddr0 = sbase + aBase * 256;

    float rval[4];
    int   ridx[4];
    #pragma unroll
    for (int i = 0; i < 4; ++i) { rval[i] = 3.0e38f; ridx[i] = 0; }

    for (int kt = 0; kt < NT; ++kt) {
        const int st = kt & 1;
        const int k0 = kb + kt * BK;

        CP_WAIT0();
        __syncthreads();
        if (kt + 1 < NT) { stage_b(st ^ 1, k0 + BK); CP_COMMIT(); }

        const uint32_t bAddr = sbase + 65536 + st * 65536 + bBase * 256;

        float acc[2][4][4];           // [bi][nb][c]  (32 cols per warp)
        #pragma unroll
        for (int bi = 0; bi < 2; ++bi)
            #pragma unroll
            for (int nb = 0; nb < 4; ++nb)
                #pragma unroll
                for (int c = 0; c < 4; ++c) acc[bi][nb][c] = 0.0f;

        #pragma unroll
        for (int kk = 0; kk < 8; ++kk) {
            uint32_t a[2][2][4];                 // [plane][bi]
            #pragma unroll
            for (int pl = 0; pl < 2; ++pl)
                #pragma unroll
                for (int bi = 0; bi < 2; ++bi) {
                    uint32_t ad = aAddr0 + pl * 32768 + bi * 4096 +
                                  (((2 * kk + aG) ^ sxa) << 4);
                    LDSM_X4(a[pl][bi][0], a[pl][bi][1], a[pl][bi][2], a[pl][bi][3], ad);
                }
            uint32_t b[2][2][4];                 // [plane][nquad of 16 cols]
            #pragma unroll
            for (int pl = 0; pl < 2; ++pl)
                #pragma unroll
                for (int i = 0; i < 2; ++i) {
                    uint32_t bd = bAddr + pl * 32768 + i * 4096 +
                                  (((2 * kk + bG) ^ sxb) << 4);
                    LDSM_X4(b[pl][i][0], b[pl][i][1], b[pl][i][2], b[pl][i][3], bd);
                }
            // 4 exact split products: A0B0 + A0B1 + A1B0 + A1B1, same accum
            #pragma unroll
            for (int ap = 0; ap < 2; ++ap)
                #pragma unroll
                for (int bp = 0; bp < 2; ++bp)
                    #pragma unroll
                    for (int bi = 0; bi < 2; ++bi)
                        #pragma unroll
                        for (int nb = 0; nb < 4; ++nb) {
                            const uint32_t* q = b[bp][nb >> 1];
                            if (nb & 1) MMA_BF16(acc[bi][nb], a[ap][bi], q[2], q[3]);
                            else        MMA_BF16(acc[bi][nb], a[ap][bi], q[0], q[1]);
                        }
        }

        // ---- fused argmin epilogue (k ascends per slot; strict '<' = first
        //      occurrence, jnp.argmin tie rule) ----
        #pragma unroll
        for (int bi = 0; bi < 2; ++bi)
            #pragma unroll
            for (int nb = 0; nb < 4; ++nb) {
                int ncol = 32 * wn + 8 * nb + 2 * (L & 3);
                float2 c2p = __ldg((const float2*)(g_c2 + k0 + ncol));
                int kidx = k0 + ncol;
                #pragma unroll
                for (int h = 0; h < 2; ++h) {
                    int r = bi * 2 + h;
                    float s0 = fmaf(-2.0f, acc[bi][nb][h * 2 + 0], c2p.x);
                    float s1 = fmaf(-2.0f, acc[bi][nb][h * 2 + 1], c2p.y);
                    if (s0 < rval[r]) { rval[r] = s0; ridx[r] = kidx; }
                    if (s1 < rval[r]) { rval[r] = s1; ridx[r] = kidx + 1; }
                }
            }
    }

    // ---- intra-CTA merge (16 slots per row), then global atomicMin ----
    __syncthreads();
    float* rv = (float*)smem;                    // [128][16] reuse A region
    int*   ri = (int*)(smem + 128 * 16 * 4);     // [128][16]
    #pragma unroll
    for (int bi = 0; bi < 2; ++bi)
        #pragma unroll
        for (int h = 0; h < 2; ++h) {
            int row  = 32 * wm + 16 * bi + 8 * h + (L >> 2);
            int slot = wn * 4 + (L & 3);
            rv[row * 16 + slot] = rval[bi * 2 + h];
            ri[row * 16 + slot] = ridx[bi * 2 + h];
        }
    __syncthreads();
    if (tid < BN) {
        float bv = rv[tid * 16];
        int   bi = ri[tid * 16];
        #pragma unroll
        for (int c = 1; c < 16; ++c) {
            float v  = rv[tid * 16 + c];
            int   id = ri[tid * 16 + c];
            if (v < bv || (v == bv && id < bi)) { bv = v; bi = id; }
        }
        unsigned long long key =
            ((unsigned long long)fkey(bv) << 32) | (unsigned int)bi;
        atomicMin(&g_best[n0 + tid], key);
    }
}

// ---------------------------------------------------------------------------
extern "C" void kernel_launch(void* const* d_in, const int* in_sizes, int n_in,
                              void* d_out, int out_size) {
    const float* latent;
    const float* coords;
    if (in_sizes[0] == NPTS * DIM) {
        latent = (const float*)d_in[0];
        coords = (const float*)d_in[1];
    } else {
        latent = (const float*)d_in[1];
        coords = (const float*)d_in[0];
    }
    float* out = (float*)d_out;

    const int smem_bytes = 196608;   // A 64K + B 2x64K
    cudaFuncSetAttribute(nn_hmma_kernel,
                         cudaFuncAttributeMaxDynamicSharedMemorySize, smem_bytes);

    init_best_kernel<<<NPTS / 256, 256>>>();
    split_lat_kernel<<<(NPTS * DIM) / 256, 256>>>(latent);
    split_coo_kernel<<<(KC * DIM) / 256, 256>>>(coords);
    c2_kernel<<<KC / 8, 256>>>(coords);
    nn_hmma_kernel<<<(NPTS / BN) * 2, NTHREADS, smem_bytes>>>();
    final_kernel<<<NPTS / 256, 256>>>(out);
}